// round 5
// baseline (speedup 1.0000x reference)
#include <cuda_runtime.h>
#include <cuda_fp16.h>
#include <math.h>
#include <stdint.h>

#define NN   96
#define HH   192
#define TPB  256
#define RPT  (8 * 32)    // 8 warps x 32 rows per warp
#define EPSV 1e-6f

// ---------------- smem layout (bytes) ----------------
#define OFF_G     0
#define OFF_B     384
#define OFF_DHI   1024
#define STR_D     208
#define SZ_D      (96 * 208)
#define OFF_DLO   (OFF_DHI + SZ_D)
#define OFF_W1HI  (OFF_DLO + SZ_D)
#define STR_W1    208
#define SZ_W1     (192 * 208)
#define OFF_W1LO  (OFF_W1HI + SZ_W1)
#define OFF_W2HI  (OFF_W1LO + SZ_W1)
#define STR_W2    400
#define SZ_W2     (96 * 400)
#define OFF_W2LO  (OFF_W2HI + SZ_W2)
#define SMEM_TOTAL (OFF_W2LO + SZ_W2)    // 197632

__device__ __forceinline__ uint32_t smem_u32(const void* p) {
    uint32_t a;
    asm("{ .reg .u64 t; cvta.to.shared.u64 t, %1; cvt.u32.u64 %0, t; }" : "=r"(a) : "l"(p));
    return a;
}

#define LDSM4(d0, d1, d2, d3, a) \
    asm volatile("ldmatrix.sync.aligned.m8n8.x4.shared.b16 {%0,%1,%2,%3}, [%4];" \
        : "=r"(d0), "=r"(d1), "=r"(d2), "=r"(d3) : "r"(a))

#define LDSM2(d0, d1, a) \
    asm volatile("ldmatrix.sync.aligned.m8n8.x2.shared.b16 {%0,%1}, [%2];" \
        : "=r"(d0), "=r"(d1) : "r"(a))

#define MMA(ac, A, b0, b1) \
    asm volatile("mma.sync.aligned.m16n8k16.row.col.f32.f16.f16.f32 " \
        "{%0,%1,%2,%3}, {%4,%5,%6,%7}, {%8,%9}, {%0,%1,%2,%3};" \
        : "+f"((ac)[0]), "+f"((ac)[1]), "+f"((ac)[2]), "+f"((ac)[3]) \
        : "r"((A)[0]), "r"((A)[1]), "r"((A)[2]), "r"((A)[3]), "r"(b0), "r"(b1))

__device__ __forceinline__ void sp2(float a, float b, uint32_t& hi, uint32_t& lo) {
    __half2 h = __floats2half2_rn(a, b);
    float ra = a - __low2float(h);
    float rb = b - __high2float(h);
    __half2 l = __floats2half2_rn(ra, rb);
    hi = *(uint32_t*)&h;
    lo = *(uint32_t*)&l;
}

// 6-mma split group over k32 for one 4-float accumulator
#define MMA6(ac, A0h, A0l, A1h, A1l, B_h, B_l)       \
    do {                                             \
        MMA(ac, A0h, (B_h)[0], (B_h)[1]);            \
        MMA(ac, A0h, (B_l)[0], (B_l)[1]);            \
        MMA(ac, A0l, (B_h)[0], (B_h)[1]);            \
        MMA(ac, A1h, (B_h)[2], (B_h)[3]);            \
        MMA(ac, A1h, (B_l)[2], (B_l)[3]);            \
        MMA(ac, A1l, (B_h)[2], (B_h)[3]);            \
    } while (0)

extern __shared__ char sm[];

__global__ void __launch_bounds__(TPB, 1)
fused_mma_kernel(const float* __restrict__ x,
                 const float* __restrict__ W1,
                 const float* __restrict__ W2,
                 const float* __restrict__ gamma,
                 const float* __restrict__ beta,
                 float* __restrict__ out,
                 int rows) {
    const int tid  = threadIdx.x;
    const int lane = tid & 31;
    const int warp = tid >> 5;
    const int gid  = lane >> 2;
    const int tig  = lane & 3;
    const uint32_t sb = smem_u32(sm);

    float* sg  = (float*)(sm + OFF_G);
    float* sbt = (float*)(sm + OFF_B);

    // ---------------- one-time weight staging ----------------
    if (tid < 96) { sg[tid] = gamma[tid]; sbt[tid] = beta[tid]; }
    const float PI192 = 0.016362461737446838f;
    for (int t = tid; t < 96 * 96; t += TPB) {
        int n = t / 96, i = t % 96;
        int m = ((2 * i + 1) * n) % 384;
        float v = 2.0f * cosf(PI192 * (float)m);
        __half h = __float2half_rn(v);
        __half l = __float2half_rn(v - __half2float(h));
        *(__half*)(sm + OFF_DHI + n * STR_D + i * 2) = h;
        *(__half*)(sm + OFF_DLO + n * STR_D + i * 2) = l;
    }
    for (int t = tid; t < 192 * 96; t += TPB) {
        int n = t / 96, i = t % 96;
        float v = W1[t];
        __half h = __float2half_rn(v);
        __half l = __float2half_rn(v - __half2float(h));
        *(__half*)(sm + OFF_W1HI + n * STR_W1 + i * 2) = h;
        *(__half*)(sm + OFF_W1LO + n * STR_W1 + i * 2) = l;
    }
    for (int t = tid; t < 96 * 192; t += TPB) {
        int n = t / 192, i = t % 192;
        float v = W2[t];
        __half h = __float2half_rn(v);
        __half l = __float2half_rn(v - __half2float(h));
        *(__half*)(sm + OFF_W2HI + n * STR_W2 + i * 2) = h;
        *(__half*)(sm + OFF_W2LO + n * STR_W2 + i * 2) = l;
    }
    __syncthreads();

    const uint32_t lrow = lane & 7;
    const uint32_t lkb  = (uint32_t)(lane >> 3) * 16;
    const uint32_t lkb2 = (uint32_t)((lane >> 3) & 1) * 16;
    const uint32_t bDh  = sb + OFF_DHI  + lrow * STR_D  + lkb;
    const uint32_t bDl  = sb + OFF_DLO  + lrow * STR_D  + lkb;
    const uint32_t bW1h = sb + OFF_W1HI + lrow * STR_W1 + lkb;
    const uint32_t bW1l = sb + OFF_W1LO + lrow * STR_W1 + lkb;
    const uint32_t bW2h = sb + OFF_W2HI + lrow * STR_W2 + lkb2;
    const uint32_t bW2l = sb + OFF_W2LO + lrow * STR_W2 + lkb2;

    const int ntiles = (rows + RPT - 1) / RPT;

    for (int tile = blockIdx.x; tile < ntiles; tile += gridDim.x) {
        const int r0 = tile * RPT + warp * 32 + gid;   // group A rows: r0, r0+8
        const int r2 = r0 + 16;                        // group B rows: r2, r2+8
        const float* xr0 = x + (size_t)min(r0,      rows - 1) * NN;
        const float* xr1 = x + (size_t)min(r0 + 8,  rows - 1) * NN;
        const float* xr2 = x + (size_t)min(r2,      rows - 1) * NN;
        const float* xr3 = x + (size_t)min(r2 + 8,  rows - 1) * NN;

        // ================= GEMM1: Y = X @ D^T  (M=32) =================
        float acc[12][8];
#pragma unroll
        for (int i = 0; i < 12; i++)
#pragma unroll
            for (int q = 0; q < 8; q++) acc[i][q] = 0.f;

#pragma unroll
        for (int ktp = 0; ktp < 3; ktp++) {
            uint32_t Ah0[4], Al0[4], Ah1[4], Al1[4];   // group A
            uint32_t Bh0[4], Bl0[4], Bh1[4], Bl1[4];   // group B
            {
                int kb = 32 * ktp + 2 * tig;
                float2 v;
                v = *(const float2*)(xr0 + kb);      sp2(v.x, v.y, Ah0[0], Al0[0]);
                v = *(const float2*)(xr1 + kb);      sp2(v.x, v.y, Ah0[1], Al0[1]);
                v = *(const float2*)(xr0 + kb + 8);  sp2(v.x, v.y, Ah0[2], Al0[2]);
                v = *(const float2*)(xr1 + kb + 8);  sp2(v.x, v.y, Ah0[3], Al0[3]);
                v = *(const float2*)(xr0 + kb + 16); sp2(v.x, v.y, Ah1[0], Al1[0]);
                v = *(const float2*)(xr1 + kb + 16); sp2(v.x, v.y, Ah1[1], Al1[1]);
                v = *(const float2*)(xr0 + kb + 24); sp2(v.x, v.y, Ah1[2], Al1[2]);
                v = *(const float2*)(xr1 + kb + 24); sp2(v.x, v.y, Ah1[3], Al1[3]);
                v = *(const float2*)(xr2 + kb);      sp2(v.x, v.y, Bh0[0], Bl0[0]);
                v = *(const float2*)(xr3 + kb);      sp2(v.x, v.y, Bh0[1], Bl0[1]);
                v = *(const float2*)(xr2 + kb + 8);  sp2(v.x, v.y, Bh0[2], Bl0[2]);
                v = *(const float2*)(xr3 + kb + 8);  sp2(v.x, v.y, Bh0[3], Bl0[3]);
                v = *(const float2*)(xr2 + kb + 16); sp2(v.x, v.y, Bh1[0], Bl1[0]);
                v = *(const float2*)(xr3 + kb + 16); sp2(v.x, v.y, Bh1[1], Bl1[1]);
                v = *(const float2*)(xr2 + kb + 24); sp2(v.x, v.y, Bh1[2], Bl1[2]);
                v = *(const float2*)(xr3 + kb + 24); sp2(v.x, v.y, Bh1[3], Bl1[3]);
            }
#pragma unroll
            for (int g = 0; g < 3; g++) {
#pragma unroll
                for (int j = 0; j < 4; j++) {
                    uint32_t wh[4], wl[4];
                    int nt = 4 * g + j;
                    LDSM4(wh[0], wh[1], wh[2], wh[3], bDh + nt * (8 * STR_D) + ktp * 64);
                    LDSM4(wl[0], wl[1], wl[2], wl[3], bDl + nt * (8 * STR_D) + ktp * 64);
                    MMA6(acc[nt],     Ah0, Al0, Ah1, Al1, wh, wl);
                    MMA6(acc[nt] + 4, Bh0, Bl0, Bh1, Bl1, wh, wl);
                }
            }
        }

        // ================= LayerNorm 1 (4 rows) =================
        float s0 = 0.f, s1 = 0.f, s2 = 0.f, s3 = 0.f;
#pragma unroll
        for (int nt = 0; nt < 12; nt++) {
            s0 += acc[nt][0] + acc[nt][1]; s1 += acc[nt][2] + acc[nt][3];
            s2 += acc[nt][4] + acc[nt][5]; s3 += acc[nt][6] + acc[nt][7];
        }
        s0 += __shfl_xor_sync(~0u, s0, 1); s0 += __shfl_xor_sync(~0u, s0, 2);
        s1 += __shfl_xor_sync(~0u, s1, 1); s1 += __shfl_xor_sync(~0u, s1, 2);
        s2 += __shfl_xor_sync(~0u, s2, 1); s2 += __shfl_xor_sync(~0u, s2, 2);
        s3 += __shfl_xor_sync(~0u, s3, 1); s3 += __shfl_xor_sync(~0u, s3, 2);
        float mu0 = s0 * (1.f/96.f), mu1 = s1 * (1.f/96.f), mu2 = s2 * (1.f/96.f), mu3 = s3 * (1.f/96.f);
        float q0 = 0.f, q1 = 0.f, q2 = 0.f, q3 = 0.f;
#pragma unroll
        for (int nt = 0; nt < 12; nt++) {
            float d;
            d = acc[nt][0] - mu0; q0 = fmaf(d, d, q0);
            d = acc[nt][1] - mu0; q0 = fmaf(d, d, q0);
            d = acc[nt][2] - mu1; q1 = fmaf(d, d, q1);
            d = acc[nt][3] - mu1; q1 = fmaf(d, d, q1);
            d = acc[nt][4] - mu2; q2 = fmaf(d, d, q2);
            d = acc[nt][5] - mu2; q2 = fmaf(d, d, q2);
            d = acc[nt][6] - mu3; q3 = fmaf(d, d, q3);
            d = acc[nt][7] - mu3; q3 = fmaf(d, d, q3);
        }
        q0 += __shfl_xor_sync(~0u, q0, 1); q0 += __shfl_xor_sync(~0u, q0, 2);
        q1 += __shfl_xor_sync(~0u, q1, 1); q1 += __shfl_xor_sync(~0u, q1, 2);
        q2 += __shfl_xor_sync(~0u, q2, 1); q2 += __shfl_xor_sync(~0u, q2, 2);
        q3 += __shfl_xor_sync(~0u, q3, 1); q3 += __shfl_xor_sync(~0u, q3, 2);
        float rs0 = rsqrtf(q0 * (1.f/96.f) + EPSV);
        float rs1 = rsqrtf(q1 * (1.f/96.f) + EPSV);
        float rs2 = rsqrtf(q2 * (1.f/96.f) + EPSV);
        float rs3 = rsqrtf(q3 * (1.f/96.f) + EPSV);

        // LN -> GEMM2 A-fragments (acc reused/freed here)
        uint32_t a2h[6][8], a2l[6][8];
#pragma unroll
        for (int nt = 0; nt < 12; nt++) {
            float2 gv = *(const float2*)(sg  + 8 * nt + 2 * tig);
            float2 bv = *(const float2*)(sbt + 8 * nt + 2 * tig);
            float e0 = fmaf((acc[nt][0] - mu0) * rs0, gv.x, bv.x);
            float e1 = fmaf((acc[nt][1] - mu0) * rs0, gv.y, bv.y);
            float e2 = fmaf((acc[nt][2] - mu1) * rs1, gv.x, bv.x);
            float e3 = fmaf((acc[nt][3] - mu1) * rs1, gv.y, bv.y);
            float e4 = fmaf((acc[nt][4] - mu2) * rs2, gv.x, bv.x);
            float e5 = fmaf((acc[nt][5] - mu2) * rs2, gv.y, bv.y);
            float e6 = fmaf((acc[nt][6] - mu3) * rs3, gv.x, bv.x);
            float e7 = fmaf((acc[nt][7] - mu3) * rs3, gv.y, bv.y);
            int kk = nt >> 1, of = (nt & 1) * 2;
            sp2(e0, e1, a2h[kk][of],     a2l[kk][of]);
            sp2(e2, e3, a2h[kk][of + 1], a2l[kk][of + 1]);
            sp2(e4, e5, a2h[kk][of + 4], a2l[kk][of + 4]);
            sp2(e6, e7, a2h[kk][of + 5], a2l[kk][of + 5]);
        }

        // ========== Fused GEMM2 (relu) -> GEMM3, streaming k16 h-chunks ==========
        float sfr[12][8];
#pragma unroll
        for (int i = 0; i < 12; i++)
#pragma unroll
            for (int q = 0; q < 8; q++) sfr[i][q] = 0.f;

#pragma unroll
        for (int gg = 0; gg < 12; gg++) {
            // GEMM2 for n-tiles 2gg, 2gg+1 (K=96), both row groups
            float ac2[2][8];
#pragma unroll
            for (int j = 0; j < 2; j++)
#pragma unroll
                for (int q = 0; q < 8; q++) ac2[j][q] = 0.f;
#pragma unroll
            for (int ktp = 0; ktp < 3; ktp++) {
#pragma unroll
                for (int j = 0; j < 2; j++) {
                    uint32_t wh[4], wl[4];
                    int nt = 2 * gg + j;
                    LDSM4(wh[0], wh[1], wh[2], wh[3], bW1h + nt * (8 * STR_W1) + ktp * 64);
                    LDSM4(wl[0], wl[1], wl[2], wl[3], bW1l + nt * (8 * STR_W1) + ktp * 64);
                    MMA6(ac2[j],     a2h[2*ktp],   a2l[2*ktp],   a2h[2*ktp+1],   a2l[2*ktp+1],   wh, wl);
                    MMA6(ac2[j] + 4, a2h[2*ktp]+4, a2l[2*ktp]+4, a2h[2*ktp+1]+4, a2l[2*ktp+1]+4, wh, wl);
                }
            }
            // relu + pack into one k16 h A-fragment per row group
            uint32_t hAh[4], hAl[4], hBh[4], hBl[4];
            sp2(fmaxf(ac2[0][0],0.f), fmaxf(ac2[0][1],0.f), hAh[0], hAl[0]);
            sp2(fmaxf(ac2[0][2],0.f), fmaxf(ac2[0][3],0.f), hAh[1], hAl[1]);
            sp2(fmaxf(ac2[1][0],0.f), fmaxf(ac2[1][1],0.f), hAh[2], hAl[2]);
            sp2(fmaxf(ac2[1][2],0.f), fmaxf(ac2[1][3],0.f), hAh[3], hAl[3]);
            sp2(fmaxf(ac2[0][4],0.f), fmaxf(ac2[0][5],0.f), hBh[0], hBl[0]);
            sp2(fmaxf(ac2[0][6],0.f), fmaxf(ac2[0][7],0.f), hBh[1], hBl[1]);
            sp2(fmaxf(ac2[1][4],0.f), fmaxf(ac2[1][5],0.f), hBh[2], hBl[2]);
            sp2(fmaxf(ac2[1][6],0.f), fmaxf(ac2[1][7],0.f), hBh[3], hBl[3]);

            // GEMM3 k16 update over 12 n-tiles
#pragma unroll
            for (int j = 0; j < 12; j++) {
                uint32_t w0h, w1h, w0l, w1l;
                LDSM2(w0h, w1h, bW2h + j * (8 * STR_W2) + gg * 32);
                LDSM2(w0l, w1l, bW2l + j * (8 * STR_W2) + gg * 32);
                MMA(sfr[j],     hAh, w0h, w1h);
                MMA(sfr[j],     hAh, w0l, w1l);
                MMA(sfr[j],     hAl, w0h, w1h);
                MMA(sfr[j] + 4, hBh, w0h, w1h);
                MMA(sfr[j] + 4, hBh, w0l, w1l);
                MMA(sfr[j] + 4, hBl, w0h, w1h);
            }
        }

        // ================= sigmoid + LayerNorm 2 + output =================
#pragma unroll
        for (int nt = 0; nt < 12; nt++)
#pragma unroll
            for (int q = 0; q < 8; q++)
                sfr[nt][q] = 1.0f / (1.0f + __expf(-sfr[nt][q]));

        float t0 = 0.f, t1 = 0.f, t2 = 0.f, t3 = 0.f;
#pragma unroll
        for (int nt = 0; nt < 12; nt++) {
            t0 += sfr[nt][0] + sfr[nt][1]; t1 += sfr[nt][2] + sfr[nt][3];
            t2 += sfr[nt][4] + sfr[nt][5]; t3 += sfr[nt][6] + sfr[nt][7];
        }
        t0 += __shfl_xor_sync(~0u, t0, 1); t0 += __shfl_xor_sync(~0u, t0, 2);
        t1 += __shfl_xor_sync(~0u, t1, 1); t1 += __shfl_xor_sync(~0u, t1, 2);
        t2 += __shfl_xor_sync(~0u, t2, 1); t2 += __shfl_xor_sync(~0u, t2, 2);
        t3 += __shfl_xor_sync(~0u, t3, 1); t3 += __shfl_xor_sync(~0u, t3, 2);
        float m0 = t0 * (1.f/96.f), m1 = t1 * (1.f/96.f), m2 = t2 * (1.f/96.f), m3 = t3 * (1.f/96.f);
        float p0 = 0.f, p1 = 0.f, p2 = 0.f, p3 = 0.f;
#pragma unroll
        for (int nt = 0; nt < 12; nt++) {
            float d;
            d = sfr[nt][0] - m0; p0 = fmaf(d, d, p0);
            d = sfr[nt][1] - m0; p0 = fmaf(d, d, p0);
            d = sfr[nt][2] - m1; p1 = fmaf(d, d, p1);
            d = sfr[nt][3] - m1; p1 = fmaf(d, d, p1);
            d = sfr[nt][4] - m2; p2 = fmaf(d, d, p2);
            d = sfr[nt][5] - m2; p2 = fmaf(d, d, p2);
            d = sfr[nt][6] - m3; p3 = fmaf(d, d, p3);
            d = sfr[nt][7] - m3; p3 = fmaf(d, d, p3);
        }
        p0 += __shfl_xor_sync(~0u, p0, 1); p0 += __shfl_xor_sync(~0u, p0, 2);
        p1 += __shfl_xor_sync(~0u, p1, 1); p1 += __shfl_xor_sync(~0u, p1, 2);
        p2 += __shfl_xor_sync(~0u, p2, 1); p2 += __shfl_xor_sync(~0u, p2, 2);
        p3 += __shfl_xor_sync(~0u, p3, 1); p3 += __shfl_xor_sync(~0u, p3, 2);
        float z0 = rsqrtf(p0 * (1.f/96.f) + EPSV);
        float z1 = rsqrtf(p1 * (1.f/96.f) + EPSV);
        float z2 = rsqrtf(p2 * (1.f/96.f) + EPSV);
        float z3 = rsqrtf(p3 * (1.f/96.f) + EPSV);

#pragma unroll
        for (int nt = 0; nt < 12; nt++) {
            int col = 8 * nt + 2 * tig;
            float2 gv = *(const float2*)(sg  + col);
            float2 bv = *(const float2*)(sbt + col);
            int rr[4] = { r0, r0 + 8, r2, r2 + 8 };
            float mm[4] = { m0, m1, m2, m3 };
            float zz[4] = { z0, z1, z2, z3 };
#pragma unroll
            for (int g = 0; g < 4; g++) {
                if (rr[g] < rows) {
                    float wa = fmaf((sfr[nt][2 * g]     - mm[g]) * zz[g], gv.x, bv.x);
                    float wb = fmaf((sfr[nt][2 * g + 1] - mm[g]) * zz[g], gv.y, bv.y);
                    float2 xv = *(const float2*)(x + (size_t)rr[g] * NN + col);
                    float2 o; o.x = xv.x * wa; o.y = xv.y * wb;
                    *(float2*)(out + (size_t)rr[g] * NN + col) = o;
                }
            }
        }
    }
}

extern "C" void kernel_launch(void* const* d_in, const int* in_sizes, int n_in,
                              void* d_out, int out_size) {
    const float* x     = (const float*)d_in[0];
    const float* W1    = (const float*)d_in[1];
    const float* W2    = (const float*)d_in[2];
    const float* gamma = (const float*)d_in[3];
    const float* beta  = (const float*)d_in[4];
    float* out = (float*)d_out;

    int rows = in_sizes[0] / NN;

    cudaFuncSetAttribute(fused_mma_kernel, cudaFuncAttributeMaxDynamicSharedMemorySize, SMEM_TOTAL);
    fused_mma_kernel<<<152, TPB, SMEM_TOTAL>>>(x, W1, W2, gamma, beta, out, rows);
}

// round 7
// speedup vs baseline: 1.2115x; 1.2115x over previous
#include <cuda_runtime.h>
#include <cuda_fp16.h>
#include <math.h>
#include <stdint.h>

#define NN   96
#define HH   192
#define TPB  384
#define RPT  (12 * 16)   // 12 warps x m16 rows
#define EPSV 1e-6f

// ---------------- smem layout (bytes) ----------------
#define OFF_G     0
#define OFF_B     384
#define OFF_DHI   1024
#define STR_D     208
#define SZ_D      (96 * 208)
#define OFF_DLO   (OFF_DHI + SZ_D)
#define OFF_W1HI  (OFF_DLO + SZ_D)
#define STR_W1    208
#define SZ_W1     (192 * 208)
#define OFF_W1LO  (OFF_W1HI + SZ_W1)
#define OFF_W2HI  (OFF_W1LO + SZ_W1)
#define STR_W2    400
#define SZ_W2     (96 * 400)
#define OFF_W2LO  (OFF_W2HI + SZ_W2)
#define SMEM_TOTAL (OFF_W2LO + SZ_W2)    // 197632

__device__ __forceinline__ uint32_t smem_u32(const void* p) {
    uint32_t a;
    asm("{ .reg .u64 t; cvta.to.shared.u64 t, %1; cvt.u32.u64 %0, t; }" : "=r"(a) : "l"(p));
    return a;
}

#define LDSM4(d0, d1, d2, d3, a) \
    asm volatile("ldmatrix.sync.aligned.m8n8.x4.shared.b16 {%0,%1,%2,%3}, [%4];" \
        : "=r"(d0), "=r"(d1), "=r"(d2), "=r"(d3) : "r"(a))

#define MMA(ac, A, b0, b1) \
    asm volatile("mma.sync.aligned.m16n8k16.row.col.f32.f16.f16.f32 " \
        "{%0,%1,%2,%3}, {%4,%5,%6,%7}, {%8,%9}, {%0,%1,%2,%3};" \
        : "+f"((ac)[0]), "+f"((ac)[1]), "+f"((ac)[2]), "+f"((ac)[3]) \
        : "r"((A)[0]), "r"((A)[1]), "r"((A)[2]), "r"((A)[3]), "r"(b0), "r"(b1))

__device__ __forceinline__ void sp2(float a, float b, uint32_t& hi, uint32_t& lo) {
    __half2 h = __floats2half2_rn(a, b);
    float ra = a - __low2float(h);
    float rb = b - __high2float(h);
    __half2 l = __floats2half2_rn(ra, rb);
    hi = *(uint32_t*)&h;
    lo = *(uint32_t*)&l;
}

__device__ __forceinline__ float fast_sigmoid(float v) {
    float t;
    asm("tanh.approx.f32 %0, %1;" : "=f"(t) : "f"(v * 0.5f));
    return fmaf(t, 0.5f, 0.5f);
}

extern __shared__ char sm[];

__global__ void __launch_bounds__(TPB, 1)
fused_mma_kernel(const float* __restrict__ x,
                 const float* __restrict__ W1,
                 const float* __restrict__ W2,
                 const float* __restrict__ gamma,
                 const float* __restrict__ beta,
                 float* __restrict__ out,
                 int rows) {
    const int tid  = threadIdx.x;
    const int lane = tid & 31;
    const int warp = tid >> 5;
    const int gid  = lane >> 2;
    const int tig  = lane & 3;
    const uint32_t sb = smem_u32(sm);

    float* sg  = (float*)(sm + OFF_G);
    float* sbt = (float*)(sm + OFF_B);

    // ---------------- one-time weight staging ----------------
    if (tid < 96) { sg[tid] = gamma[tid]; sbt[tid] = beta[tid]; }
    const float PI192 = 0.016362461737446838f;
    for (int t = tid; t < 96 * 96; t += TPB) {
        int n = t / 96, i = t % 96;
        int m = ((2 * i + 1) * n) % 384;
        float v = 2.0f * cosf(PI192 * (float)m);
        __half h = __float2half_rn(v);
        __half l = __float2half_rn(v - __half2float(h));
        *(__half*)(sm + OFF_DHI + n * STR_D + i * 2) = h;
        *(__half*)(sm + OFF_DLO + n * STR_D + i * 2) = l;
    }
    for (int t = tid; t < 192 * 96; t += TPB) {
        int n = t / 96, i = t % 96;
        float v = W1[t];
        __half h = __float2half_rn(v);
        __half l = __float2half_rn(v - __half2float(h));
        *(__half*)(sm + OFF_W1HI + n * STR_W1 + i * 2) = h;
        *(__half*)(sm + OFF_W1LO + n * STR_W1 + i * 2) = l;
    }
    for (int t = tid; t < 96 * 192; t += TPB) {
        int n = t / 192, i = t % 192;
        float v = W2[t];
        __half h = __float2half_rn(v);
        __half l = __float2half_rn(v - __half2float(h));
        *(__half*)(sm + OFF_W2HI + n * STR_W2 + i * 2) = h;
        *(__half*)(sm + OFF_W2LO + n * STR_W2 + i * 2) = l;
    }
    __syncthreads();

    const uint32_t lrow = lane & 7;
    const uint32_t lkb  = (uint32_t)(lane >> 3) * 16;
    const uint32_t bDh  = sb + OFF_DHI  + lrow * STR_D  + lkb;
    const uint32_t bDl  = sb + OFF_DLO  + lrow * STR_D  + lkb;
    const uint32_t bW1h = sb + OFF_W1HI + lrow * STR_W1 + lkb;
    const uint32_t bW1l = sb + OFF_W1LO + lrow * STR_W1 + lkb;
    const uint32_t bW2h = sb + OFF_W2HI + lrow * STR_W2 + lkb;   // LDSM4 -> full lkb
    const uint32_t bW2l = sb + OFF_W2LO + lrow * STR_W2 + lkb;

    const int ntiles = (rows + RPT - 1) / RPT;

    for (int tile = blockIdx.x; tile < ntiles; tile += gridDim.x) {
        const int r0 = tile * RPT + warp * 16 + gid;
        const int r1 = r0 + 8;
        const float* xr0 = x + (size_t)min(r0, rows - 1) * NN;
        const float* xr1 = x + (size_t)min(r1, rows - 1) * NN;

        // ================= GEMM1: Y = X @ D^T =================
        float acc[12][4];
#pragma unroll
        for (int i = 0; i < 12; i++) { acc[i][0] = acc[i][1] = acc[i][2] = acc[i][3] = 0.f; }

#pragma unroll
        for (int ktp = 0; ktp < 3; ktp++) {
            uint32_t ah0[4], al0[4], ah1[4], al1[4];
            {
                int kb = 32 * ktp + 2 * tig;
                float2 v;
                v = *(const float2*)(xr0 + kb);      sp2(v.x, v.y, ah0[0], al0[0]);
                v = *(const float2*)(xr1 + kb);      sp2(v.x, v.y, ah0[1], al0[1]);
                v = *(const float2*)(xr0 + kb + 8);  sp2(v.x, v.y, ah0[2], al0[2]);
                v = *(const float2*)(xr1 + kb + 8);  sp2(v.x, v.y, ah0[3], al0[3]);
                v = *(const float2*)(xr0 + kb + 16); sp2(v.x, v.y, ah1[0], al1[0]);
                v = *(const float2*)(xr1 + kb + 16); sp2(v.x, v.y, ah1[1], al1[1]);
                v = *(const float2*)(xr0 + kb + 24); sp2(v.x, v.y, ah1[2], al1[2]);
                v = *(const float2*)(xr1 + kb + 24); sp2(v.x, v.y, ah1[3], al1[3]);
            }
#pragma unroll
            for (int g = 0; g < 3; g++) {
                uint32_t bh[4][4], bl[4][4];
#pragma unroll
                for (int j = 0; j < 4; j++) {
                    int nt = 4 * g + j;
                    LDSM4(bh[j][0], bh[j][1], bh[j][2], bh[j][3], bDh + nt * (8 * STR_D) + ktp * 64);
                    LDSM4(bl[j][0], bl[j][1], bl[j][2], bl[j][3], bDl + nt * (8 * STR_D) + ktp * 64);
                }
#pragma unroll
                for (int j = 0; j < 4; j++) MMA(acc[4 * g + j], ah0, bh[j][0], bh[j][1]);
#pragma unroll
                for (int j = 0; j < 4; j++) MMA(acc[4 * g + j], ah0, bl[j][0], bl[j][1]);
#pragma unroll
                for (int j = 0; j < 4; j++) MMA(acc[4 * g + j], al0, bh[j][0], bh[j][1]);
#pragma unroll
                for (int j = 0; j < 4; j++) MMA(acc[4 * g + j], ah1, bh[j][2], bh[j][3]);
#pragma unroll
                for (int j = 0; j < 4; j++) MMA(acc[4 * g + j], ah1, bl[j][2], bl[j][3]);
#pragma unroll
                for (int j = 0; j < 4; j++) MMA(acc[4 * g + j], al1, bh[j][2], bh[j][3]);
            }
        }

        // ================= LayerNorm 1 =================
        float s0 = 0.f, s1 = 0.f;
#pragma unroll
        for (int nt = 0; nt < 12; nt++) { s0 += acc[nt][0] + acc[nt][1]; s1 += acc[nt][2] + acc[nt][3]; }
        s0 += __shfl_xor_sync(~0u, s0, 1); s0 += __shfl_xor_sync(~0u, s0, 2);
        s1 += __shfl_xor_sync(~0u, s1, 1); s1 += __shfl_xor_sync(~0u, s1, 2);
        float mu0 = s0 * (1.f/96.f), mu1 = s1 * (1.f/96.f);
        float q0 = 0.f, q1 = 0.f;
#pragma unroll
        for (int nt = 0; nt < 12; nt++) {
            float d;
            d = acc[nt][0] - mu0; q0 = fmaf(d, d, q0);
            d = acc[nt][1] - mu0; q0 = fmaf(d, d, q0);
            d = acc[nt][2] - mu1; q1 = fmaf(d, d, q1);
            d = acc[nt][3] - mu1; q1 = fmaf(d, d, q1);
        }
        q0 += __shfl_xor_sync(~0u, q0, 1); q0 += __shfl_xor_sync(~0u, q0, 2);
        q1 += __shfl_xor_sync(~0u, q1, 1); q1 += __shfl_xor_sync(~0u, q1, 2);
        float rs0 = rsqrtf(q0 * (1.f/96.f) + EPSV);
        float rs1 = rsqrtf(q1 * (1.f/96.f) + EPSV);

        // LN -> GEMM2 A-fragments
        uint32_t a2h[6][4], a2l[6][4];
#pragma unroll
        for (int nt = 0; nt < 12; nt++) {
            float2 gv = *(const float2*)(sg  + 8 * nt + 2 * tig);
            float2 bv = *(const float2*)(sbt + 8 * nt + 2 * tig);
            float e0 = fmaf((acc[nt][0] - mu0) * rs0, gv.x, bv.x);
            float e1 = fmaf((acc[nt][1] - mu0) * rs0, gv.y, bv.y);
            float e2 = fmaf((acc[nt][2] - mu1) * rs1, gv.x, bv.x);
            float e3 = fmaf((acc[nt][3] - mu1) * rs1, gv.y, bv.y);
            int kk = nt >> 1, of = (nt & 1) * 2;
            sp2(e0, e1, a2h[kk][of],     a2l[kk][of]);
            sp2(e2, e3, a2h[kk][of + 1], a2l[kk][of + 1]);
        }

        // ========== Fused GEMM2 (relu) -> GEMM3 streaming over h-chunks ==========
        float sfr[12][4];
#pragma unroll
        for (int i = 0; i < 12; i++) { sfr[i][0] = sfr[i][1] = sfr[i][2] = sfr[i][3] = 0.f; }

#pragma unroll
        for (int g = 0; g < 6; g++) {
            // GEMM2 for n-tiles 4g..4g+3 (K=96) — batched LDSM then MMAs per k-step
            float ac2[4][4];
#pragma unroll
            for (int j = 0; j < 4; j++) { ac2[j][0] = ac2[j][1] = ac2[j][2] = ac2[j][3] = 0.f; }
#pragma unroll
            for (int ktp = 0; ktp < 3; ktp++) {
                uint32_t wh[4][4], wl[4][4];
#pragma unroll
                for (int j = 0; j < 4; j++) {
                    int nt = 4 * g + j;
                    LDSM4(wh[j][0], wh[j][1], wh[j][2], wh[j][3], bW1h + nt * (8 * STR_W1) + ktp * 64);
                    LDSM4(wl[j][0], wl[j][1], wl[j][2], wl[j][3], bW1l + nt * (8 * STR_W1) + ktp * 64);
                }
#pragma unroll
                for (int j = 0; j < 4; j++) MMA(ac2[j], a2h[2*ktp],     wh[j][0], wh[j][1]);
#pragma unroll
                for (int j = 0; j < 4; j++) MMA(ac2[j], a2h[2*ktp],     wl[j][0], wl[j][1]);
#pragma unroll
                for (int j = 0; j < 4; j++) MMA(ac2[j], a2l[2*ktp],     wh[j][0], wh[j][1]);
#pragma unroll
                for (int j = 0; j < 4; j++) MMA(ac2[j], a2h[2*ktp + 1], wh[j][2], wh[j][3]);
#pragma unroll
                for (int j = 0; j < 4; j++) MMA(ac2[j], a2h[2*ktp + 1], wl[j][2], wl[j][3]);
#pragma unroll
                for (int j = 0; j < 4; j++) MMA(ac2[j], a2l[2*ktp + 1], wh[j][2], wh[j][3]);
            }
            // relu + pack -> GEMM3 k32 A-fragments
            uint32_t h0h[4], h0l[4], h1h[4], h1l[4];
            sp2(fmaxf(ac2[0][0],0.f), fmaxf(ac2[0][1],0.f), h0h[0], h0l[0]);
            sp2(fmaxf(ac2[0][2],0.f), fmaxf(ac2[0][3],0.f), h0h[1], h0l[1]);
            sp2(fmaxf(ac2[1][0],0.f), fmaxf(ac2[1][1],0.f), h0h[2], h0l[2]);
            sp2(fmaxf(ac2[1][2],0.f), fmaxf(ac2[1][3],0.f), h0h[3], h0l[3]);
            sp2(fmaxf(ac2[2][0],0.f), fmaxf(ac2[2][1],0.f), h1h[0], h1l[0]);
            sp2(fmaxf(ac2[2][2],0.f), fmaxf(ac2[2][3],0.f), h1h[1], h1l[1]);
            sp2(fmaxf(ac2[3][0],0.f), fmaxf(ac2[3][1],0.f), h1h[2], h1l[2]);
            sp2(fmaxf(ac2[3][2],0.f), fmaxf(ac2[3][3],0.f), h1h[3], h1l[3]);

            // GEMM3 k32 update, n-tiles batched in groups of 4
#pragma unroll
            for (int jb = 0; jb < 3; jb++) {
                uint32_t vh[4][4], vl[4][4];
#pragma unroll
                for (int j = 0; j < 4; j++) {
                    int nt = 4 * jb + j;
                    LDSM4(vh[j][0], vh[j][1], vh[j][2], vh[j][3], bW2h + nt * (8 * STR_W2) + g * 64);
                    LDSM4(vl[j][0], vl[j][1], vl[j][2], vl[j][3], bW2l + nt * (8 * STR_W2) + g * 64);
                }
#pragma unroll
                for (int j = 0; j < 4; j++) MMA(sfr[4*jb+j], h0h, vh[j][0], vh[j][1]);
#pragma unroll
                for (int j = 0; j < 4; j++) MMA(sfr[4*jb+j], h0h, vl[j][0], vl[j][1]);
#pragma unroll
                for (int j = 0; j < 4; j++) MMA(sfr[4*jb+j], h0l, vh[j][0], vh[j][1]);
#pragma unroll
                for (int j = 0; j < 4; j++) MMA(sfr[4*jb+j], h1h, vh[j][2], vh[j][3]);
#pragma unroll
                for (int j = 0; j < 4; j++) MMA(sfr[4*jb+j], h1h, vl[j][2], vl[j][3]);
#pragma unroll
                for (int j = 0; j < 4; j++) MMA(sfr[4*jb+j], h1l, vh[j][2], vh[j][3]);
            }
        }

        // ================= sigmoid + LayerNorm 2 + output =================
#pragma unroll
        for (int nt = 0; nt < 12; nt++)
#pragma unroll
            for (int q = 0; q < 4; q++)
                sfr[nt][q] = fast_sigmoid(sfr[nt][q]);

        float t0 = 0.f, t1 = 0.f;
#pragma unroll
        for (int nt = 0; nt < 12; nt++) { t0 += sfr[nt][0] + sfr[nt][1]; t1 += sfr[nt][2] + sfr[nt][3]; }
        t0 += __shfl_xor_sync(~0u, t0, 1); t0 += __shfl_xor_sync(~0u, t0, 2);
        t1 += __shfl_xor_sync(~0u, t1, 1); t1 += __shfl_xor_sync(~0u, t1, 2);
        float m20 = t0 * (1.f/96.f), m21 = t1 * (1.f/96.f);
        float p0 = 0.f, p1 = 0.f;
#pragma unroll
        for (int nt = 0; nt < 12; nt++) {
            float d;
            d = sfr[nt][0] - m20; p0 = fmaf(d, d, p0);
            d = sfr[nt][1] - m20; p0 = fmaf(d, d, p0);
            d = sfr[nt][2] - m21; p1 = fmaf(d, d, p1);
            d = sfr[nt][3] - m21; p1 = fmaf(d, d, p1);
        }
        p0 += __shfl_xor_sync(~0u, p0, 1); p0 += __shfl_xor_sync(~0u, p0, 2);
        p1 += __shfl_xor_sync(~0u, p1, 1); p1 += __shfl_xor_sync(~0u, p1, 2);
        float rz0 = rsqrtf(p0 * (1.f/96.f) + EPSV);
        float rz1 = rsqrtf(p1 * (1.f/96.f) + EPSV);

#pragma unroll
        for (int nt = 0; nt < 12; nt++) {
            int col = 8 * nt + 2 * tig;
            float2 gv = *(const float2*)(sg  + col);
            float2 bv = *(const float2*)(sbt + col);
            float w00 = fmaf((sfr[nt][0] - m20) * rz0, gv.x, bv.x);
            float w01 = fmaf((sfr[nt][1] - m20) * rz0, gv.y, bv.y);
            float w10 = fmaf((sfr[nt][2] - m21) * rz1, gv.x, bv.x);
            float w11 = fmaf((sfr[nt][3] - m21) * rz1, gv.y, bv.y);
            if (r0 < rows) {
                float2 xv = *(const float2*)(x + (size_t)r0 * NN + col);
                float2 o; o.x = xv.x * w00; o.y = xv.y * w01;
                *(float2*)(out + (size_t)r0 * NN + col) = o;
            }
            if (r1 < rows) {
                float2 xv = *(const float2*)(x + (size_t)r1 * NN + col);
                float2 o; o.x = xv.x * w10; o.y = xv.y * w11;
                *(float2*)(out + (size_t)r1 * NN + col) = o;
            }
        }
    }
}

extern "C" void kernel_launch(void* const* d_in, const int* in_sizes, int n_in,
                              void* d_out, int out_size) {
    const float* x     = (const float*)d_in[0];
    const float* W1    = (const float*)d_in[1];
    const float* W2    = (const float*)d_in[2];
    const float* gamma = (const float*)d_in[3];
    const float* beta  = (const float*)d_in[4];
    float* out = (float*)d_out;

    int rows = in_sizes[0] / NN;

    cudaFuncSetAttribute(fused_mma_kernel, cudaFuncAttributeMaxDynamicSharedMemorySize, SMEM_TOTAL);
    fused_mma_kernel<<<152, TPB, SMEM_TOTAL>>>(x, W1, W2, gamma, beta, out, rows);
}